// round 2
// baseline (speedup 1.0000x reference)
#include <cuda_runtime.h>
#include <cstdint>
#include <math.h>

#define N_NODES 10000
#define N_EDGES 320000
#define N_GRAPHS 64
#define HID 256

// ---------------- scratch (static __device__, no allocation) ----------------
__device__ __align__(16) float g_h [N_NODES * HID];
__device__ __align__(16) float g_t1[N_NODES * HID];
__device__ __align__(16) float g_t2[N_NODES * HID];
__device__ int   g_deg[N_NODES];
__device__ int   g_off[N_NODES + 1];
__device__ int   g_cur[N_NODES];
__device__ int   g_csr[N_EDGES];
__device__ int   g_cnt[N_GRAPHS];

__device__ __forceinline__ float silu(float v) {
    return v / (1.0f + expf(-v));
}

__device__ __forceinline__ int clampi(int v, int hi) {
    return v < 0 ? 0 : (v >= hi ? hi - 1 : v);
}

// ---------------- embed: h = silu(x * W_emb + b_emb) ----------------
__global__ void embed_kernel(const float* __restrict__ x,
                             const float* __restrict__ w,
                             const float* __restrict__ b) {
    int idx = blockIdx.x * blockDim.x + threadIdx.x;
    if (idx >= N_NODES * HID) return;
    int n = idx >> 8;
    int d = idx & 255;
    g_h[idx] = silu(x[n] * w[d] + b[d]);
}

// ---------------- CSR build ----------------
__global__ void zero_deg_kernel() {
    int i = blockIdx.x * blockDim.x + threadIdx.x;
    if (i < N_NODES) g_deg[i] = 0;
}

__global__ void hist_kernel(const int* __restrict__ dst) {
    int e = blockIdx.x * blockDim.x + threadIdx.x;
    if (e < N_EDGES) atomicAdd(&g_deg[clampi(dst[e], N_NODES)], 1);
}

// single-block exclusive scan over 10000 degrees; also zeroes cursors
__global__ void scan_kernel() {
    __shared__ int sh[1024];
    __shared__ int carry;
    int tid = threadIdx.x;
    if (tid == 0) carry = 0;
    __syncthreads();
    for (int base = 0; base < N_NODES; base += 1024) {
        int i = base + tid;
        int v = (i < N_NODES) ? g_deg[i] : 0;
        sh[tid] = v;
        __syncthreads();
        for (int o = 1; o < 1024; o <<= 1) {
            int t = (tid >= o) ? sh[tid - o] : 0;
            __syncthreads();
            sh[tid] += t;
            __syncthreads();
        }
        if (i < N_NODES) {
            g_off[i] = carry + sh[tid] - v;   // exclusive
            g_cur[i] = 0;
        }
        __syncthreads();
        if (tid == 1023) carry += sh[1023];
        __syncthreads();
    }
    if (tid == 0) g_off[N_NODES] = carry;
}

__global__ void fill_kernel(const int* __restrict__ src,
                            const int* __restrict__ dst) {
    int e = blockIdx.x * blockDim.x + threadIdx.x;
    if (e < N_EDGES) {
        int d = clampi(dst[e], N_NODES);
        int p = g_off[d] + atomicAdd(&g_cur[d], 1);
        if (p >= 0 && p < N_EDGES)
            g_csr[p] = clampi(src[e], N_NODES);
    }
}

// ---------------- GEMM: C = act(A[M,256] @ W[256,256] + bias) ----------------
// 128x128x32 tile, 256 threads, 8x8 per thread.
#define BM 128
#define BN 128
#define BK 32
#define TM 8
#define TN 8

template <bool RELU>
__global__ __launch_bounds__(256, 2)
void gemm_kernel(const float* __restrict__ A,
                 const float* __restrict__ W,
                 const float* __restrict__ bias,
                 float* __restrict__ C, int M) {
    __shared__ float As[BK][BM];
    __shared__ float Bs[BK][BN];
    int tid = threadIdx.x;
    int tx = tid & 15;          // col group 0..15
    int ty = tid >> 4;          // row group 0..15
    int rowBase = blockIdx.x * BM;
    int colBase = blockIdx.y * BN;

    float acc[TM][TN];
#pragma unroll
    for (int i = 0; i < TM; i++)
#pragma unroll
        for (int j = 0; j < TN; j++) acc[i][j] = 0.0f;

    for (int kt = 0; kt < HID; kt += BK) {
        // load A tile: 128 rows x 32 k -> 1024 float4, 4 per thread (store transposed)
#pragma unroll
        for (int i = 0; i < 4; i++) {
            int l = tid + 256 * i;
            int r  = l >> 3;       // 0..127
            int kq = l & 7;        // 0..7  (k = kq*4)
            int grow = rowBase + r;
            float4 v = make_float4(0.f, 0.f, 0.f, 0.f);
            if (grow < M)
                v = *(const float4*)(A + (size_t)grow * HID + kt + kq * 4);
            As[kq * 4 + 0][r] = v.x;
            As[kq * 4 + 1][r] = v.y;
            As[kq * 4 + 2][r] = v.z;
            As[kq * 4 + 3][r] = v.w;
        }
        // load B tile: 32 k-rows x 128 cols -> 1024 float4, 4 per thread
#pragma unroll
        for (int i = 0; i < 4; i++) {
            int l = tid + 256 * i;
            int r  = l >> 5;       // 0..31
            int cq = l & 31;       // 0..31
            float4 v = *(const float4*)(W + (size_t)(kt + r) * HID + colBase + cq * 4);
            *(float4*)(&Bs[r][cq * 4]) = v;
        }
        __syncthreads();

#pragma unroll
        for (int k = 0; k < BK; k++) {
            float ra[TM], rb[TN];
            *(float4*)(&ra[0]) = *(const float4*)(&As[k][ty * TM]);
            *(float4*)(&ra[4]) = *(const float4*)(&As[k][ty * TM + 4]);
            *(float4*)(&rb[0]) = *(const float4*)(&Bs[k][tx * TN]);
            *(float4*)(&rb[4]) = *(const float4*)(&Bs[k][tx * TN + 4]);
#pragma unroll
            for (int i = 0; i < TM; i++)
#pragma unroll
                for (int j = 0; j < TN; j++)
                    acc[i][j] += ra[i] * rb[j];
        }
        __syncthreads();
    }

#pragma unroll
    for (int i = 0; i < TM; i++) {
        int grow = rowBase + ty * TM + i;
        if (grow < M) {
#pragma unroll
            for (int j = 0; j < TN; j += 4) {
                int gcol = colBase + tx * TN + j;
                float4 v;
                v.x = acc[i][j + 0] + bias[gcol + 0];
                v.y = acc[i][j + 1] + bias[gcol + 1];
                v.z = acc[i][j + 2] + bias[gcol + 2];
                v.w = acc[i][j + 3] + bias[gcol + 3];
                if (RELU) {
                    v.x = fmaxf(v.x, 0.f); v.y = fmaxf(v.y, 0.f);
                    v.z = fmaxf(v.z, 0.f); v.w = fmaxf(v.w, 0.f);
                }
                *(float4*)(C + (size_t)grow * HID + gcol) = v;
            }
        }
    }
}

// ---------------- edge aggregation: h[n] += silu(max_{e in in(n)} t2[src[e]]) ----------------
__global__ void agg_kernel() {
    int n = blockIdx.x;
    int tid = threadIdx.x;      // 256 = feature dim
    int s = g_off[n], e = g_off[n + 1];
    __shared__ int sh[256];
    float m0 = -INFINITY, m1 = -INFINITY, m2 = -INFINITY, m3 = -INFINITY;

    for (int base = s; base < e; base += 256) {
        int cnt = min(256, e - base);
        if (tid < cnt) sh[tid] = g_csr[base + tid];
        __syncthreads();
        int j = 0;
        for (; j + 4 <= cnt; j += 4) {
            float v0 = g_t2[(size_t)sh[j + 0] * HID + tid];
            float v1 = g_t2[(size_t)sh[j + 1] * HID + tid];
            float v2 = g_t2[(size_t)sh[j + 2] * HID + tid];
            float v3 = g_t2[(size_t)sh[j + 3] * HID + tid];
            m0 = fmaxf(m0, v0); m1 = fmaxf(m1, v1);
            m2 = fmaxf(m2, v2); m3 = fmaxf(m3, v3);
        }
        for (; j < cnt; j++)
            m0 = fmaxf(m0, g_t2[(size_t)sh[j] * HID + tid]);
        __syncthreads();
    }
    float m = fmaxf(fmaxf(m0, m1), fmaxf(m2, m3));
    float v = (e > s) ? m : 0.0f;     // PyG: nodes with no incoming msgs -> 0
    g_h[(size_t)n * HID + tid] += silu(v);
}

// ---------------- global mean pool ----------------
__global__ void pool_zero_kernel(float* __restrict__ out) {
    int i = blockIdx.x * blockDim.x + threadIdx.x;
    if (i < N_GRAPHS * HID) out[i] = 0.0f;
    if (i < N_GRAPHS) g_cnt[i] = 0;
}

__global__ void pool_count_kernel(const int* __restrict__ batch) {
    int n = blockIdx.x * blockDim.x + threadIdx.x;
    if (n < N_NODES) atomicAdd(&g_cnt[clampi(batch[n], N_GRAPHS)], 1);
}

__global__ void pool_accum_kernel(const int* __restrict__ batch,
                                  float* __restrict__ out) {
    int idx = blockIdx.x * blockDim.x + threadIdx.x;
    if (idx >= N_NODES * HID) return;
    int n = idx >> 8;
    int d = idx & 255;
    int g = clampi(batch[n], N_GRAPHS);
    atomicAdd(&out[g * HID + d], g_h[idx]);
}

__global__ void pool_div_kernel(float* __restrict__ out) {
    int i = blockIdx.x * blockDim.x + threadIdx.x;
    if (i >= N_GRAPHS * HID) return;
    int g = i >> 8;
    float c = (float)g_cnt[g];
    out[i] /= fmaxf(c, 1.0f);
}

// ---------------- launch ----------------
extern "C" void kernel_launch(void* const* d_in, const int* in_sizes, int n_in,
                              void* d_out, int out_size) {
    const float* x     = (const float*)d_in[0];
    const int*   ei    = (const int*)d_in[1];
    const int*   batch = (const int*)d_in[2];
    const float* W_emb = (const float*)d_in[3];
    const float* b_emb = (const float*)d_in[4];
    const float* W1a   = (const float*)d_in[5];
    const float* b1a   = (const float*)d_in[6];
    const float* W1b   = (const float*)d_in[7];
    const float* b1b   = (const float*)d_in[8];
    const float* W2a   = (const float*)d_in[9];
    const float* b2a   = (const float*)d_in[10];
    const float* W2b   = (const float*)d_in[11];
    const float* b2b   = (const float*)d_in[12];
    float* out = (float*)d_out;

    const int* src = ei;            // edge_index row 0
    const int* dst = ei + N_EDGES;  // edge_index row 1

    float* h  = nullptr; float* t1 = nullptr; float* t2 = nullptr;
    cudaGetSymbolAddress((void**)&h,  g_h);
    cudaGetSymbolAddress((void**)&t1, g_t1);
    cudaGetSymbolAddress((void**)&t2, g_t2);

    // embed
    embed_kernel<<<(N_NODES * HID + 255) / 256, 256>>>(x, W_emb, b_emb);

    // CSR build (once; both convs share the edges)
    zero_deg_kernel<<<(N_NODES + 255) / 256, 256>>>();
    hist_kernel<<<(N_EDGES + 255) / 256, 256>>>(dst);
    scan_kernel<<<1, 1024>>>();
    fill_kernel<<<(N_EDGES + 255) / 256, 256>>>(src, dst);

    dim3 ggrid((N_NODES + BM - 1) / BM, HID / BN);

    // conv 1: t1 = relu(h@W1a+b1a); t2 = t1@W1b+b1b; h += silu(gather-max)
    gemm_kernel<true ><<<ggrid, 256>>>(h,  W1a, b1a, t1, N_NODES);
    gemm_kernel<false><<<ggrid, 256>>>(t1, W1b, b1b, t2, N_NODES);
    agg_kernel<<<N_NODES, 256>>>();

    // conv 2
    gemm_kernel<true ><<<ggrid, 256>>>(h,  W2a, b2a, t1, N_NODES);
    gemm_kernel<false><<<ggrid, 256>>>(t1, W2b, b2b, t2, N_NODES);
    agg_kernel<<<N_NODES, 256>>>();

    // global mean pool
    pool_zero_kernel<<<(N_GRAPHS * HID + 255) / 256, 256>>>(out);
    pool_count_kernel<<<(N_NODES + 255) / 256, 256>>>(batch);
    pool_accum_kernel<<<(N_NODES * HID + 255) / 256, 256>>>(batch, out);
    pool_div_kernel<<<(N_GRAPHS * HID + 255) / 256, 256>>>(out);
}

// round 3
// speedup vs baseline: 1.7673x; 1.7673x over previous
#include <cuda_runtime.h>
#include <cstdint>
#include <math.h>

#define N_NODES 10000
#define N_EDGES 320000
#define N_GRAPHS 64
#define HID 256

// ---------------- scratch (static __device__, no allocation) ----------------
__device__ __align__(16) float g_h [N_NODES * HID];
__device__ __align__(16) float g_t1[N_NODES * HID];
__device__ __align__(16) float g_t2[N_NODES * HID];
__device__ int   g_deg[N_NODES];
__device__ int   g_off[N_NODES + 1];
__device__ int   g_cur[N_NODES];
__device__ int   g_csr[N_EDGES];
__device__ int   g_cnt[N_GRAPHS];

__device__ __forceinline__ float silu(float v) {
    return v / (1.0f + expf(-v));
}

__device__ __forceinline__ int clampi(int v, int hi) {
    return v < 0 ? 0 : (v >= hi ? hi - 1 : v);
}

__device__ __forceinline__ unsigned f2tf32(float f) {
    unsigned r;
    asm("cvt.rna.tf32.f32 %0, %1;" : "=r"(r) : "f"(f));
    return r;
}

__device__ __forceinline__ void mma_tf32(float* d, const unsigned* a, const unsigned* b) {
    asm volatile(
        "mma.sync.aligned.m16n8k8.row.col.f32.tf32.tf32.f32 "
        "{%0,%1,%2,%3}, {%4,%5,%6,%7}, {%8,%9}, {%0,%1,%2,%3};"
        : "+f"(d[0]), "+f"(d[1]), "+f"(d[2]), "+f"(d[3])
        : "r"(a[0]), "r"(a[1]), "r"(a[2]), "r"(a[3]),
          "r"(b[0]), "r"(b[1]));
}

// ---------------- embed: h = silu(x * W_emb + b_emb) ----------------
__global__ void embed_kernel(const float* __restrict__ x,
                             const float* __restrict__ w,
                             const float* __restrict__ b) {
    int idx = blockIdx.x * blockDim.x + threadIdx.x;
    if (idx >= N_NODES * HID) return;
    int n = idx >> 8;
    int d = idx & 255;
    g_h[idx] = silu(x[n] * w[d] + b[d]);
}

// ---------------- CSR build ----------------
__global__ void zero_deg_kernel() {
    int i = blockIdx.x * blockDim.x + threadIdx.x;
    if (i < N_NODES) g_deg[i] = 0;
}

__global__ void hist_kernel(const int* __restrict__ dst) {
    int e = blockIdx.x * blockDim.x + threadIdx.x;
    if (e < N_EDGES) atomicAdd(&g_deg[clampi(dst[e], N_NODES)], 1);
}

// fast single-block scan: 1024 threads x 10 elems, warp-shuffle based
__global__ void scan_kernel() {
    const int VT = 10;                 // 1024*10 = 10240 >= 10000
    __shared__ int wsum[32];
    int tid = threadIdx.x;
    int lane = tid & 31, w = tid >> 5;
    int base = tid * VT;

    int excl[VT];
    int s = 0;
#pragma unroll
    for (int j = 0; j < VT; j++) {
        int i = base + j;
        int v = (i < N_NODES) ? g_deg[i] : 0;
        excl[j] = s;
        s += v;
    }
    // warp inclusive scan of per-thread sums
    int x = s;
#pragma unroll
    for (int o = 1; o < 32; o <<= 1) {
        int y = __shfl_up_sync(0xffffffffu, x, o);
        if (lane >= o) x += y;
    }
    if (lane == 31) wsum[w] = x;
    __syncthreads();
    if (w == 0) {
        int y = wsum[lane];
#pragma unroll
        for (int o = 1; o < 32; o <<= 1) {
            int z = __shfl_up_sync(0xffffffffu, y, o);
            if (lane >= o) y += z;
        }
        wsum[lane] = y;
    }
    __syncthreads();
    int warpBase = (w > 0) ? wsum[w - 1] : 0;
    int tbase = warpBase + x - s;      // exclusive base for this thread
#pragma unroll
    for (int j = 0; j < VT; j++) {
        int i = base + j;
        if (i < N_NODES) {
            g_off[i] = tbase + excl[j];
            g_cur[i] = 0;
        }
    }
    if (tid == 1023) g_off[N_NODES] = wsum[31];
}

__global__ void fill_kernel(const int* __restrict__ src,
                            const int* __restrict__ dst) {
    int e = blockIdx.x * blockDim.x + threadIdx.x;
    if (e < N_EDGES) {
        int d = clampi(dst[e], N_NODES);
        int p = g_off[d] + atomicAdd(&g_cur[d], 1);
        if (p >= 0 && p < N_EDGES)
            g_csr[p] = clampi(src[e], N_NODES);
    }
}

// ---------------- tensor-core GEMM: C = act(A[M,256] @ W[256,256] + bias) ----
// tf32 mma.sync m16n8k8. 128x128 block tile, BK=32, 256 threads (8 warps).
// Warp grid 2x4: each warp computes 64 rows x 32 cols = 4x4 mma tiles.
#define BM 128
#define BN 128
#define BK 32

template <bool RELU>
__global__ __launch_bounds__(256, 2)
void gemm_tc(const float* __restrict__ A,
             const float* __restrict__ W,
             const float* __restrict__ bias,
             float* __restrict__ C, int M) {
    // strides chosen so fragment LDS are conflict-free:
    // As[m][k] stride 36 (36 mod 32 = 4), Bs[k][n] stride 132 (132 mod 32 = 4)
    __shared__ unsigned As[BM][BK + 4];
    __shared__ unsigned Bs[BK][BN + 4];

    int tid  = threadIdx.x;
    int lane = tid & 31;
    int warp = tid >> 5;
    int wr = (warp & 1) * 64;        // warp row offset in tile
    int wc = (warp >> 1) * 32;       // warp col offset in tile
    int rowBase = blockIdx.x * BM;
    int colBase = blockIdx.y * BN;
    int g  = lane >> 2;              // group id 0..7
    int t4 = lane & 3;               // thread-in-group 0..3

    float acc[4][4][4];
#pragma unroll
    for (int mi = 0; mi < 4; mi++)
#pragma unroll
        for (int ni = 0; ni < 4; ni++)
#pragma unroll
            for (int r = 0; r < 4; r++) acc[mi][ni][r] = 0.0f;

    for (int kt = 0; kt < HID; kt += BK) {
        // A tile: 128 rows x 32 k -> 1024 float4, 4 per thread
#pragma unroll
        for (int i = 0; i < 4; i++) {
            int l  = tid + 256 * i;
            int r  = l >> 3;             // 0..127
            int kq = (l & 7) * 4;        // 0..28
            int grow = rowBase + r;
            float4 v = make_float4(0.f, 0.f, 0.f, 0.f);
            if (grow < M)
                v = *(const float4*)(A + (size_t)grow * HID + kt + kq);
            As[r][kq + 0] = f2tf32(v.x);
            As[r][kq + 1] = f2tf32(v.y);
            As[r][kq + 2] = f2tf32(v.z);
            As[r][kq + 3] = f2tf32(v.w);
        }
        // B tile: 32 k-rows x 128 cols -> 1024 float4, 4 per thread
#pragma unroll
        for (int i = 0; i < 4; i++) {
            int l  = tid + 256 * i;
            int r  = l >> 5;             // 0..31
            int cq = (l & 31) * 4;       // 0..124
            float4 v = *(const float4*)(W + (size_t)(kt + r) * HID + colBase + cq);
            Bs[r][cq + 0] = f2tf32(v.x);
            Bs[r][cq + 1] = f2tf32(v.y);
            Bs[r][cq + 2] = f2tf32(v.z);
            Bs[r][cq + 3] = f2tf32(v.w);
        }
        __syncthreads();

#pragma unroll
        for (int s = 0; s < 4; s++) {
            int k0 = s * 8;
            unsigned a[4][4], b[4][2];
#pragma unroll
            for (int mi = 0; mi < 4; mi++) {
                int m0 = wr + mi * 16;
                a[mi][0] = As[m0 + g    ][k0 + t4    ];
                a[mi][1] = As[m0 + g + 8][k0 + t4    ];
                a[mi][2] = As[m0 + g    ][k0 + t4 + 4];
                a[mi][3] = As[m0 + g + 8][k0 + t4 + 4];
            }
#pragma unroll
            for (int ni = 0; ni < 4; ni++) {
                int n0 = wc + ni * 8;
                b[ni][0] = Bs[k0 + t4    ][n0 + g];
                b[ni][1] = Bs[k0 + t4 + 4][n0 + g];
            }
#pragma unroll
            for (int mi = 0; mi < 4; mi++)
#pragma unroll
                for (int ni = 0; ni < 4; ni++)
                    mma_tf32(acc[mi][ni], a[mi], b[ni]);
        }
        __syncthreads();
    }

    // epilogue: bias + activation, float2 stores
#pragma unroll
    for (int mi = 0; mi < 4; mi++) {
        int row0 = rowBase + wr + mi * 16 + g;
        int row1 = row0 + 8;
#pragma unroll
        for (int ni = 0; ni < 4; ni++) {
            int col = colBase + wc + ni * 8 + t4 * 2;
            float b0 = bias[col], b1 = bias[col + 1];
            if (row0 < M) {
                float2 v;
                v.x = acc[mi][ni][0] + b0;
                v.y = acc[mi][ni][1] + b1;
                if (RELU) { v.x = fmaxf(v.x, 0.f); v.y = fmaxf(v.y, 0.f); }
                *(float2*)(C + (size_t)row0 * HID + col) = v;
            }
            if (row1 < M) {
                float2 v;
                v.x = acc[mi][ni][2] + b0;
                v.y = acc[mi][ni][3] + b1;
                if (RELU) { v.x = fmaxf(v.x, 0.f); v.y = fmaxf(v.y, 0.f); }
                *(float2*)(C + (size_t)row1 * HID + col) = v;
            }
        }
    }
}

// ---------------- edge aggregation: h[n] += silu(max_{e in in(n)} t2[src[e]]) ----------------
__global__ void agg_kernel() {
    int n = blockIdx.x;
    int tid = threadIdx.x;      // 256 = feature dim
    int s = g_off[n], e = g_off[n + 1];
    __shared__ int sh[256];
    float m0 = -INFINITY, m1 = -INFINITY, m2 = -INFINITY, m3 = -INFINITY;

    for (int base = s; base < e; base += 256) {
        int cnt = min(256, e - base);
        if (tid < cnt) sh[tid] = g_csr[base + tid];
        __syncthreads();
        int j = 0;
        for (; j + 4 <= cnt; j += 4) {
            float v0 = g_t2[(size_t)sh[j + 0] * HID + tid];
            float v1 = g_t2[(size_t)sh[j + 1] * HID + tid];
            float v2 = g_t2[(size_t)sh[j + 2] * HID + tid];
            float v3 = g_t2[(size_t)sh[j + 3] * HID + tid];
            m0 = fmaxf(m0, v0); m1 = fmaxf(m1, v1);
            m2 = fmaxf(m2, v2); m3 = fmaxf(m3, v3);
        }
        for (; j < cnt; j++)
            m0 = fmaxf(m0, g_t2[(size_t)sh[j] * HID + tid]);
        __syncthreads();
    }
    float m = fmaxf(fmaxf(m0, m1), fmaxf(m2, m3));
    float v = (e > s) ? m : 0.0f;     // PyG: nodes with no incoming msgs -> 0
    g_h[(size_t)n * HID + tid] += silu(v);
}

// ---------------- global mean pool ----------------
__global__ void pool_zero_kernel(float* __restrict__ out) {
    int i = blockIdx.x * blockDim.x + threadIdx.x;
    if (i < N_GRAPHS * HID) out[i] = 0.0f;
    if (i < N_GRAPHS) g_cnt[i] = 0;
}

__global__ void pool_count_kernel(const int* __restrict__ batch) {
    int n = blockIdx.x * blockDim.x + threadIdx.x;
    if (n < N_NODES) atomicAdd(&g_cnt[clampi(batch[n], N_GRAPHS)], 1);
}

__global__ void pool_accum_kernel(const int* __restrict__ batch,
                                  float* __restrict__ out) {
    int idx = blockIdx.x * blockDim.x + threadIdx.x;
    if (idx >= N_NODES * HID) return;
    int n = idx >> 8;
    int d = idx & 255;
    int g = clampi(batch[n], N_GRAPHS);
    atomicAdd(&out[g * HID + d], g_h[idx]);
}

__global__ void pool_div_kernel(float* __restrict__ out) {
    int i = blockIdx.x * blockDim.x + threadIdx.x;
    if (i >= N_GRAPHS * HID) return;
    int g = i >> 8;
    float c = (float)g_cnt[g];
    out[i] /= fmaxf(c, 1.0f);
}

// ---------------- launch ----------------
extern "C" void kernel_launch(void* const* d_in, const int* in_sizes, int n_in,
                              void* d_out, int out_size) {
    const float* x     = (const float*)d_in[0];
    const int*   ei    = (const int*)d_in[1];
    const int*   batch = (const int*)d_in[2];
    const float* W_emb = (const float*)d_in[3];
    const float* b_emb = (const float*)d_in[4];
    const float* W1a   = (const float*)d_in[5];
    const float* b1a   = (const float*)d_in[6];
    const float* W1b   = (const float*)d_in[7];
    const float* b1b   = (const float*)d_in[8];
    const float* W2a   = (const float*)d_in[9];
    const float* b2a   = (const float*)d_in[10];
    const float* W2b   = (const float*)d_in[11];
    const float* b2b   = (const float*)d_in[12];
    float* out = (float*)d_out;

    const int* src = ei;            // edge_index row 0
    const int* dst = ei + N_EDGES;  // edge_index row 1

    float* h  = nullptr; float* t1 = nullptr; float* t2 = nullptr;
    cudaGetSymbolAddress((void**)&h,  g_h);
    cudaGetSymbolAddress((void**)&t1, g_t1);
    cudaGetSymbolAddress((void**)&t2, g_t2);

    // embed
    embed_kernel<<<(N_NODES * HID + 255) / 256, 256>>>(x, W_emb, b_emb);

    // CSR build (once; both convs share the edges)
    zero_deg_kernel<<<(N_NODES + 255) / 256, 256>>>();
    hist_kernel<<<(N_EDGES + 255) / 256, 256>>>(dst);
    scan_kernel<<<1, 1024>>>();
    fill_kernel<<<(N_EDGES + 255) / 256, 256>>>(src, dst);

    dim3 ggrid((N_NODES + BM - 1) / BM, HID / BN);

    // conv 1: t1 = relu(h@W1a+b1a); t2 = t1@W1b+b1b; h += silu(gather-max)
    gemm_tc<true ><<<ggrid, 256>>>(h,  W1a, b1a, t1, N_NODES);
    gemm_tc<false><<<ggrid, 256>>>(t1, W1b, b1b, t2, N_NODES);
    agg_kernel<<<N_NODES, 256>>>();

    // conv 2
    gemm_tc<true ><<<ggrid, 256>>>(h,  W2a, b2a, t1, N_NODES);
    gemm_tc<false><<<ggrid, 256>>>(t1, W2b, b2b, t2, N_NODES);
    agg_kernel<<<N_NODES, 256>>>();

    // global mean pool
    pool_zero_kernel<<<(N_GRAPHS * HID + 255) / 256, 256>>>(out);
    pool_count_kernel<<<(N_NODES + 255) / 256, 256>>>(batch);
    pool_accum_kernel<<<(N_NODES * HID + 255) / 256, 256>>>(batch, out);
    pool_div_kernel<<<(N_GRAPHS * HID + 255) / 256, 256>>>(out);
}

// round 5
// speedup vs baseline: 1.8929x; 1.0711x over previous
#include <cuda_runtime.h>
#include <cstdint>
#include <math.h>

#define N_NODES 10000
#define N_EDGES 320000
#define N_GRAPHS 64
#define HID 256

// ---------------- scratch (static __device__, no allocation) ----------------
__device__ __align__(16) float g_h [N_NODES * HID];
__device__ __align__(16) float g_t1[N_NODES * HID];
__device__ __align__(16) float g_t2[N_NODES * HID];
__device__ int   g_deg[N_NODES];
__device__ int   g_off[N_NODES + 1];
__device__ int   g_cur[N_NODES];
__device__ int   g_csr[N_EDGES];

__device__ __forceinline__ float silu(float v) {
    return v / (1.0f + expf(-v));
}

__device__ __forceinline__ int clampi(int v, int hi) {
    return v < 0 ? 0 : (v >= hi ? hi - 1 : v);
}

__device__ __forceinline__ unsigned f2tf32(float f) {
    unsigned r;
    asm("cvt.rna.tf32.f32 %0, %1;" : "=r"(r) : "f"(f));
    return r;
}

__device__ __forceinline__ void mma_tf32(float* d, const unsigned* a, const unsigned* b) {
    asm volatile(
        "mma.sync.aligned.m16n8k8.row.col.f32.tf32.tf32.f32 "
        "{%0,%1,%2,%3}, {%4,%5,%6,%7}, {%8,%9}, {%0,%1,%2,%3};"
        : "+f"(d[0]), "+f"(d[1]), "+f"(d[2]), "+f"(d[3])
        : "r"(a[0]), "r"(a[1]), "r"(a[2]), "r"(a[3]),
          "r"(b[0]), "r"(b[1]));
}

__device__ __forceinline__ void cp16(float* smem_dst, const float* gsrc, bool pred) {
    unsigned s = (unsigned)__cvta_generic_to_shared(smem_dst);
    int szn = pred ? 16 : 0;
    asm volatile("cp.async.ca.shared.global [%0], [%1], 16, %2;"
                 :: "r"(s), "l"(gsrc), "r"(szn));
}

// ---------------- embed: h = silu(x * W_emb + b_emb); also zero deg ----------
__global__ void embed_kernel(const float* __restrict__ x,
                             const float* __restrict__ w,
                             const float* __restrict__ b) {
    int idx = blockIdx.x * blockDim.x + threadIdx.x;
    if (idx >= N_NODES * HID) return;
    if (idx < N_NODES) g_deg[idx] = 0;
    int n = idx >> 8;
    int d = idx & 255;
    g_h[idx] = silu(x[n] * w[d] + b[d]);
}

// ---------------- CSR build ----------------
__global__ void hist_kernel(const int* __restrict__ dst) {
    int e = blockIdx.x * blockDim.x + threadIdx.x;
    if (e < N_EDGES) atomicAdd(&g_deg[clampi(dst[e], N_NODES)], 1);
}

// single-block scan: 1024 threads x 10 elems, warp-shuffle based
__global__ void scan_kernel() {
    const int VT = 10;
    __shared__ int wsum[32];
    int tid = threadIdx.x;
    int lane = tid & 31, w = tid >> 5;
    int base = tid * VT;

    int excl[VT];
    int s = 0;
#pragma unroll
    for (int j = 0; j < VT; j++) {
        int i = base + j;
        int v = (i < N_NODES) ? g_deg[i] : 0;
        excl[j] = s;
        s += v;
    }
    int x = s;
#pragma unroll
    for (int o = 1; o < 32; o <<= 1) {
        int y = __shfl_up_sync(0xffffffffu, x, o);
        if (lane >= o) x += y;
    }
    if (lane == 31) wsum[w] = x;
    __syncthreads();
    if (w == 0) {
        int y = wsum[lane];
#pragma unroll
        for (int o = 1; o < 32; o <<= 1) {
            int z = __shfl_up_sync(0xffffffffu, y, o);
            if (lane >= o) y += z;
        }
        wsum[lane] = y;
    }
    __syncthreads();
    int warpBase = (w > 0) ? wsum[w - 1] : 0;
    int tbase = warpBase + x - s;
#pragma unroll
    for (int j = 0; j < VT; j++) {
        int i = base + j;
        if (i < N_NODES) {
            g_off[i] = tbase + excl[j];
            g_cur[i] = 0;
        }
    }
    if (tid == 1023) g_off[N_NODES] = wsum[31];
}

__global__ void fill_kernel(const int* __restrict__ src,
                            const int* __restrict__ dst) {
    int e = blockIdx.x * blockDim.x + threadIdx.x;
    if (e < N_EDGES) {
        int d = clampi(dst[e], N_NODES);
        int p = g_off[d] + atomicAdd(&g_cur[d], 1);
        if (p >= 0 && p < N_EDGES)
            g_csr[p] = clampi(src[e], N_NODES);
    }
}

// ---------------- tensor-core GEMM, cp.async double-buffered --------------
// C = act(A[M,256] @ W[256,256] + bias); tf32 mma m16n8k8.
// f32 staged in smem via cp.async; cvt.rna.tf32 applied at fragment load.
#define BM 128
#define BN 128
#define BK 32
#define AS_STRIDE 36
#define BS_STRIDE 136
#define AS_BUF (BM * AS_STRIDE)   // 4608 floats
#define BS_BUF (BK * BS_STRIDE)   // 4352 floats
#define GEMM_SMEM_BYTES ((2 * AS_BUF + 2 * BS_BUF) * 4)   // 71680

template <bool RELU>
__global__ __launch_bounds__(256, 2)
void gemm_tc(const float* __restrict__ A,
             const float* __restrict__ W,
             const float* __restrict__ bias,
             float* __restrict__ C, int M) {
    extern __shared__ float dynsmem[];
    float* As = dynsmem;                 // [2][BM][AS_STRIDE]
    float* Bs = dynsmem + 2 * AS_BUF;    // [2][BK][BS_STRIDE]

    int tid  = threadIdx.x;
    int lane = tid & 31;
    int warp = tid >> 5;
    int wr = (warp & 1) * 64;
    int wc = (warp >> 1) * 32;
    int rowBase = blockIdx.x * BM;
    int colBase = blockIdx.y * BN;
    int g  = lane >> 2;
    int t4 = lane & 3;

    int ar[4], ac[4], br[4], bc[4];
#pragma unroll
    for (int i = 0; i < 4; i++) {
        int l = tid + 256 * i;
        ar[i] = l >> 3;              // 0..127
        ac[i] = (l & 7) * 4;         // 0..28
        br[i] = l >> 5;              // 0..31
        bc[i] = (l & 31) * 4;        // 0..124
    }

    float acc[4][4][4];
#pragma unroll
    for (int mi = 0; mi < 4; mi++)
#pragma unroll
        for (int ni = 0; ni < 4; ni++)
#pragma unroll
            for (int r = 0; r < 4; r++) acc[mi][ni][r] = 0.0f;

    // prefetch tile 0 into buf 0
#pragma unroll
    for (int i = 0; i < 4; i++) {
        int grow = rowBase + ar[i];
        cp16(&As[ar[i] * AS_STRIDE + ac[i]],
             A + (size_t)grow * HID + ac[i], grow < M);
        cp16(&Bs[br[i] * BS_STRIDE + bc[i]],
             W + (size_t)br[i] * HID + colBase + bc[i], true);
    }
    asm volatile("cp.async.commit_group;");

    int buf = 0;
#pragma unroll
    for (int kt = 0; kt < HID / BK; kt++) {
        asm volatile("cp.async.wait_group 0;");
        __syncthreads();

        if (kt < HID / BK - 1) {
            int k2 = (kt + 1) * BK;
            float* Ad = As + (buf ^ 1) * AS_BUF;
            float* Bd = Bs + (buf ^ 1) * BS_BUF;
#pragma unroll
            for (int i = 0; i < 4; i++) {
                int grow = rowBase + ar[i];
                cp16(&Ad[ar[i] * AS_STRIDE + ac[i]],
                     A + (size_t)grow * HID + k2 + ac[i], grow < M);
                cp16(&Bd[br[i] * BS_STRIDE + bc[i]],
                     W + (size_t)(k2 + br[i]) * HID + colBase + bc[i], true);
            }
            asm volatile("cp.async.commit_group;");
        }

        const float* Ab = As + buf * AS_BUF;
        const float* Bb = Bs + buf * BS_BUF;
#pragma unroll
        for (int s = 0; s < 4; s++) {
            int k0 = s * 8;
            unsigned a[4][4], b[4][2];
#pragma unroll
            for (int mi = 0; mi < 4; mi++) {
                int m0 = wr + mi * 16;
                a[mi][0] = f2tf32(Ab[(m0 + g    ) * AS_STRIDE + k0 + t4    ]);
                a[mi][1] = f2tf32(Ab[(m0 + g + 8) * AS_STRIDE + k0 + t4    ]);
                a[mi][2] = f2tf32(Ab[(m0 + g    ) * AS_STRIDE + k0 + t4 + 4]);
                a[mi][3] = f2tf32(Ab[(m0 + g + 8) * AS_STRIDE + k0 + t4 + 4]);
            }
#pragma unroll
            for (int ni = 0; ni < 4; ni++) {
                int n0 = wc + ni * 8;
                b[ni][0] = f2tf32(Bb[(k0 + t4    ) * BS_STRIDE + n0 + g]);
                b[ni][1] = f2tf32(Bb[(k0 + t4 + 4) * BS_STRIDE + n0 + g]);
            }
#pragma unroll
            for (int mi = 0; mi < 4; mi++)
#pragma unroll
                for (int ni = 0; ni < 4; ni++)
                    mma_tf32(acc[mi][ni], a[mi], b[ni]);
        }
        buf ^= 1;
    }

    // epilogue: bias + activation
#pragma unroll
    for (int mi = 0; mi < 4; mi++) {
        int row0 = rowBase + wr + mi * 16 + g;
        int row1 = row0 + 8;
#pragma unroll
        for (int ni = 0; ni < 4; ni++) {
            int col = colBase + wc + ni * 8 + t4 * 2;
            float b0 = bias[col], b1 = bias[col + 1];
            if (row0 < M) {
                float2 v;
                v.x = acc[mi][ni][0] + b0;
                v.y = acc[mi][ni][1] + b1;
                if (RELU) { v.x = fmaxf(v.x, 0.f); v.y = fmaxf(v.y, 0.f); }
                *(float2*)(C + (size_t)row0 * HID + col) = v;
            }
            if (row1 < M) {
                float2 v;
                v.x = acc[mi][ni][2] + b0;
                v.y = acc[mi][ni][3] + b1;
                if (RELU) { v.x = fmaxf(v.x, 0.f); v.y = fmaxf(v.y, 0.f); }
                *(float2*)(C + (size_t)row1 * HID + col) = v;
            }
        }
    }
}

// ---------------- edge aggregation: h[n] += silu(max_{e in in(n)} t2[src[e]]) ----
__global__ void agg_kernel() {
    int n = blockIdx.x;
    int tid = threadIdx.x;      // 256 = feature dim
    int s = g_off[n], e = g_off[n + 1];
    __shared__ int sh[256];
    float m0 = -INFINITY, m1 = -INFINITY, m2 = -INFINITY, m3 = -INFINITY;

    for (int base = s; base < e; base += 256) {
        int cnt = min(256, e - base);
        if (tid < cnt) sh[tid] = g_csr[base + tid];
        __syncthreads();
        int j = 0;
        for (; j + 4 <= cnt; j += 4) {
            float v0 = g_t2[(size_t)sh[j + 0] * HID + tid];
            float v1 = g_t2[(size_t)sh[j + 1] * HID + tid];
            float v2 = g_t2[(size_t)sh[j + 2] * HID + tid];
            float v3 = g_t2[(size_t)sh[j + 3] * HID + tid];
            m0 = fmaxf(m0, v0); m1 = fmaxf(m1, v1);
            m2 = fmaxf(m2, v2); m3 = fmaxf(m3, v3);
        }
        for (; j < cnt; j++)
            m0 = fmaxf(m0, g_t2[(size_t)sh[j] * HID + tid]);
        __syncthreads();
    }
    float m = fmaxf(fmaxf(m0, m1), fmaxf(m2, m3));
    float v = (e > s) ? m : 0.0f;
    g_h[(size_t)n * HID + tid] += silu(v);
}

// ---------------- global mean pool (batch is sorted) ----------------
__global__ void pool_kernel(const int* __restrict__ batch,
                            float* __restrict__ out) {
    int g = blockIdx.x;          // 0..63
    int tid = threadIdx.x;       // 0..255 feature

    int lo = 0, hi = N_NODES;
    while (lo < hi) { int m = (lo + hi) >> 1; if (batch[m] < g) lo = m + 1; else hi = m; }
    int start = lo;
    lo = start; hi = N_NODES;
    while (lo < hi) { int m = (lo + hi) >> 1; if (batch[m] < g + 1) lo = m + 1; else hi = m; }
    int end = lo;

    float s = 0.0f;
    for (int n = start; n < end; n++)
        s += g_h[(size_t)n * HID + tid];
    float c = (float)(end - start);
    out[g * HID + tid] = s / fmaxf(c, 1.0f);
}

// ---------------- launch ----------------
extern "C" void kernel_launch(void* const* d_in, const int* in_sizes, int n_in,
                              void* d_out, int out_size) {
    const float* x     = (const float*)d_in[0];
    const int*   ei    = (const int*)d_in[1];
    const int*   batch = (const int*)d_in[2];
    const float* W_emb = (const float*)d_in[3];
    const float* b_emb = (const float*)d_in[4];
    const float* W1a   = (const float*)d_in[5];
    const float* b1a   = (const float*)d_in[6];
    const float* W1b   = (const float*)d_in[7];
    const float* b1b   = (const float*)d_in[8];
    const float* W2a   = (const float*)d_in[9];
    const float* b2a   = (const float*)d_in[10];
    const float* W2b   = (const float*)d_in[11];
    const float* b2b   = (const float*)d_in[12];
    float* out = (float*)d_out;

    const int* src = ei;
    const int* dst = ei + N_EDGES;

    float* h  = nullptr; float* t1 = nullptr; float* t2 = nullptr;
    cudaGetSymbolAddress((void**)&h,  g_h);
    cudaGetSymbolAddress((void**)&t1, g_t1);
    cudaGetSymbolAddress((void**)&t2, g_t2);

    cudaFuncSetAttribute(gemm_tc<true>,
        cudaFuncAttributeMaxDynamicSharedMemorySize, GEMM_SMEM_BYTES);
    cudaFuncSetAttribute(gemm_tc<false>,
        cudaFuncAttributeMaxDynamicSharedMemorySize, GEMM_SMEM_BYTES);

    // embed (+ zero deg)
    embed_kernel<<<(N_NODES * HID + 255) / 256, 256>>>(x, W_emb, b_emb);

    // CSR build
    hist_kernel<<<(N_EDGES + 255) / 256, 256>>>(dst);
    scan_kernel<<<1, 1024>>>();
    fill_kernel<<<(N_EDGES + 255) / 256, 256>>>(src, dst);

    dim3 ggrid((N_NODES + BM - 1) / BM, HID / BN);

    // conv 1
    gemm_tc<true ><<<ggrid, 256, GEMM_SMEM_BYTES>>>(h,  W1a, b1a, t1, N_NODES);
    gemm_tc<false><<<ggrid, 256, GEMM_SMEM_BYTES>>>(t1, W1b, b1b, t2, N_NODES);
    agg_kernel<<<N_NODES, 256>>>();

    // conv 2
    gemm_tc<true ><<<ggrid, 256, GEMM_SMEM_BYTES>>>(h,  W2a, b2a, t1, N_NODES);
    gemm_tc<false><<<ggrid, 256, GEMM_SMEM_BYTES>>>(t1, W2b, b2b, t2, N_NODES);
    agg_kernel<<<N_NODES, 256>>>();

    // global mean pool (batch sorted -> contiguous ranges)
    pool_kernel<<<N_GRAPHS, 256>>>(batch, out);
}

// round 6
// speedup vs baseline: 2.7250x; 1.4396x over previous
#include <cuda_runtime.h>
#include <cuda_fp16.h>
#include <cstdint>
#include <math.h>

#define N_NODES 10000
#define N_EDGES 320000
#define N_GRAPHS 64
#define HID 256
#define ELL_CAP 128
#define FILL_BLOCKS 1250           // 1250*256 = 320000 edges

// ---------------- scratch (static __device__, no allocation) ----------------
__device__ __align__(16) float  g_h  [N_NODES * HID];
__device__ __align__(16) float  g_t1 [N_NODES * HID];
__device__ __align__(16) __half2 g_t2h[N_NODES * HID / 2];
__device__ int g_cur[N_NODES];          // zero at module load; re-zeroed by pool tail
__device__ int g_ell[N_NODES * ELL_CAP];

__device__ __forceinline__ float silu(float v) {
    return v / (1.0f + expf(-v));
}

__device__ __forceinline__ int clampi(int v, int hi) {
    return v < 0 ? 0 : (v >= hi ? hi - 1 : v);
}

__device__ __forceinline__ unsigned f2tf32(float f) {
    unsigned r;
    asm("cvt.rna.tf32.f32 %0, %1;" : "=r"(r) : "f"(f));
    return r;
}

__device__ __forceinline__ void mma_tf32(float* d, const unsigned* a, const unsigned* b) {
    asm volatile(
        "mma.sync.aligned.m16n8k8.row.col.f32.tf32.tf32.f32 "
        "{%0,%1,%2,%3}, {%4,%5,%6,%7}, {%8,%9}, {%0,%1,%2,%3};"
        : "+f"(d[0]), "+f"(d[1]), "+f"(d[2]), "+f"(d[3])
        : "r"(a[0]), "r"(a[1]), "r"(a[2]), "r"(a[3]),
          "r"(b[0]), "r"(b[1]));
}

__device__ __forceinline__ void cp16(float* smem_dst, const float* gsrc, bool pred) {
    unsigned s = (unsigned)__cvta_generic_to_shared(smem_dst);
    int szn = pred ? 16 : 0;
    asm volatile("cp.async.ca.shared.global [%0], [%1], 16, %2;"
                 :: "r"(s), "l"(gsrc), "r"(szn));
}

// ------- fused setup: ELL fill (blocks [0,FILL_BLOCKS)) + embed (rest) ------
// g_cur must be zero on entry (module load / previous call's pool tail).
__global__ void setup_kernel(const float* __restrict__ x,
                             const float* __restrict__ w,
                             const float* __restrict__ b,
                             const int* __restrict__ src,
                             const int* __restrict__ dst) {
    int blk = blockIdx.x;
    if (blk < FILL_BLOCKS) {
        int e = blk * 256 + threadIdx.x;
        if (e < N_EDGES) {
            int d = clampi(dst[e], N_NODES);
            int slot = atomicAdd(&g_cur[d], 1);
            if (slot < ELL_CAP)
                g_ell[d * ELL_CAP + slot] = clampi(src[e], N_NODES);
        }
    } else {
        int idx = (blk - FILL_BLOCKS) * 256 + threadIdx.x;
        if (idx < N_NODES * HID) {
            int n = idx >> 8;
            int d = idx & 255;
            g_h[idx] = silu(x[n] * w[d] + b[d]);
        }
    }
}

// ---------------- tensor-core GEMM, cp.async double-buffered --------------
// C = act(A[M,256] @ W[256,256] + bias); tf32 mma m16n8k8, cvt.rna at frag load.
// 64x128 block tile, 256 threads (8 warps, 2x4 grid of 32x32 warp tiles).
#define BM 64
#define BN 128
#define BK 32
#define AS_STRIDE 36
#define BS_STRIDE 136
#define AS_BUF (BM * AS_STRIDE)   // 2304 floats
#define BS_BUF (BK * BS_STRIDE)   // 4352 floats
#define GEMM_SMEM_BYTES ((2 * AS_BUF + 2 * BS_BUF) * 4)   // 53248

template <bool RELU, bool HALF_OUT>
__global__ __launch_bounds__(256, 3)
void gemm_tc(const float* __restrict__ A,
             const float* __restrict__ W,
             const float* __restrict__ bias,
             float* __restrict__ C,
             __half2* __restrict__ Ch, int M) {
    extern __shared__ float dynsmem[];
    float* As = dynsmem;                 // [2][BM][AS_STRIDE]
    float* Bs = dynsmem + 2 * AS_BUF;    // [2][BK][BS_STRIDE]

    int tid  = threadIdx.x;
    int lane = tid & 31;
    int warp = tid >> 5;
    int wr = (warp & 1) * 32;            // warp row offset (0/32)
    int wc = (warp >> 1) * 32;           // warp col offset (0/32/64/96)
    int rowBase = blockIdx.x * BM;
    int colBase = blockIdx.y * BN;
    int g  = lane >> 2;
    int t4 = lane & 3;

    // A: 64x32 = 512 float4 -> 2 per thread; B: 32x128 = 1024 float4 -> 4 per thread
    int ar[2], ac[2], br[4], bc[4];
#pragma unroll
    for (int i = 0; i < 2; i++) {
        int l = tid + 256 * i;
        ar[i] = l >> 3;              // 0..63
        ac[i] = (l & 7) * 4;         // 0..28
    }
#pragma unroll
    for (int i = 0; i < 4; i++) {
        int l = tid + 256 * i;
        br[i] = l >> 5;              // 0..31
        bc[i] = (l & 31) * 4;        // 0..124
    }

    float acc[2][4][4];
#pragma unroll
    for (int mi = 0; mi < 2; mi++)
#pragma unroll
        for (int ni = 0; ni < 4; ni++)
#pragma unroll
            for (int r = 0; r < 4; r++) acc[mi][ni][r] = 0.0f;

    // prefetch tile 0 into buf 0
#pragma unroll
    for (int i = 0; i < 2; i++) {
        int grow = rowBase + ar[i];
        cp16(&As[ar[i] * AS_STRIDE + ac[i]],
             A + (size_t)grow * HID + ac[i], grow < M);
    }
#pragma unroll
    for (int i = 0; i < 4; i++)
        cp16(&Bs[br[i] * BS_STRIDE + bc[i]],
             W + (size_t)br[i] * HID + colBase + bc[i], true);
    asm volatile("cp.async.commit_group;");

    int buf = 0;
#pragma unroll
    for (int kt = 0; kt < HID / BK; kt++) {
        asm volatile("cp.async.wait_group 0;");
        __syncthreads();

        if (kt < HID / BK - 1) {
            int k2 = (kt + 1) * BK;
            float* Ad = As + (buf ^ 1) * AS_BUF;
            float* Bd = Bs + (buf ^ 1) * BS_BUF;
#pragma unroll
            for (int i = 0; i < 2; i++) {
                int grow = rowBase + ar[i];
                cp16(&Ad[ar[i] * AS_STRIDE + ac[i]],
                     A + (size_t)grow * HID + k2 + ac[i], grow < M);
            }
#pragma unroll
            for (int i = 0; i < 4; i++)
                cp16(&Bd[br[i] * BS_STRIDE + bc[i]],
                     W + (size_t)(k2 + br[i]) * HID + colBase + bc[i], true);
            asm volatile("cp.async.commit_group;");
        }

        const float* Ab = As + buf * AS_BUF;
        const float* Bb = Bs + buf * BS_BUF;
#pragma unroll
        for (int s = 0; s < 4; s++) {
            int k0 = s * 8;
            unsigned a[2][4], b[4][2];
#pragma unroll
            for (int mi = 0; mi < 2; mi++) {
                int m0 = wr + mi * 16;
                a[mi][0] = f2tf32(Ab[(m0 + g    ) * AS_STRIDE + k0 + t4    ]);
                a[mi][1] = f2tf32(Ab[(m0 + g + 8) * AS_STRIDE + k0 + t4    ]);
                a[mi][2] = f2tf32(Ab[(m0 + g    ) * AS_STRIDE + k0 + t4 + 4]);
                a[mi][3] = f2tf32(Ab[(m0 + g + 8) * AS_STRIDE + k0 + t4 + 4]);
            }
#pragma unroll
            for (int ni = 0; ni < 4; ni++) {
                int n0 = wc + ni * 8;
                b[ni][0] = f2tf32(Bb[(k0 + t4    ) * BS_STRIDE + n0 + g]);
                b[ni][1] = f2tf32(Bb[(k0 + t4 + 4) * BS_STRIDE + n0 + g]);
            }
#pragma unroll
            for (int mi = 0; mi < 2; mi++)
#pragma unroll
                for (int ni = 0; ni < 4; ni++)
                    mma_tf32(acc[mi][ni], a[mi], b[ni]);
        }
        buf ^= 1;
    }

    // epilogue: bias + activation
#pragma unroll
    for (int mi = 0; mi < 2; mi++) {
        int row0 = rowBase + wr + mi * 16 + g;
        int row1 = row0 + 8;
#pragma unroll
        for (int ni = 0; ni < 4; ni++) {
            int col = colBase + wc + ni * 8 + t4 * 2;
            float b0 = bias[col], b1 = bias[col + 1];
            float v00 = acc[mi][ni][0] + b0, v01 = acc[mi][ni][1] + b1;
            float v10 = acc[mi][ni][2] + b0, v11 = acc[mi][ni][3] + b1;
            if (RELU) {
                v00 = fmaxf(v00, 0.f); v01 = fmaxf(v01, 0.f);
                v10 = fmaxf(v10, 0.f); v11 = fmaxf(v11, 0.f);
            }
            if (HALF_OUT) {
                if (row0 < M)
                    Ch[(size_t)row0 * (HID / 2) + (col >> 1)] =
                        __floats2half2_rn(v00, v01);
                if (row1 < M)
                    Ch[(size_t)row1 * (HID / 2) + (col >> 1)] =
                        __floats2half2_rn(v10, v11);
            } else {
                if (row0 < M)
                    *(float2*)(C + (size_t)row0 * HID + col) = make_float2(v00, v01);
                if (row1 < M)
                    *(float2*)(C + (size_t)row1 * HID + col) = make_float2(v10, v11);
            }
        }
    }
}

// ------- edge aggregation: h[n] += silu(max_{src in ELL(n)} t2h[src]) -------
// 128 threads/block; thread t handles feature pair (2t, 2t+1) via half2.
__global__ void agg_kernel() {
    int n = blockIdx.x;
    int tid = threadIdx.x;           // 0..127
    int cnt = min(g_cur[n], ELL_CAP);
    const int* lst = g_ell + n * ELL_CAP;
    __shared__ int sh[128];

    unsigned ninf = 0xFC00FC00u;     // half2(-inf, -inf)
    __half2 m0 = *(__half2*)&ninf, m1 = m0, m2 = m0, m3 = m0;

    for (int base = 0; base < cnt; base += 128) {
        int c = min(128, cnt - base);
        if (tid < c) sh[tid] = lst[base + tid];
        __syncthreads();
        int j = 0;
        for (; j + 4 <= c; j += 4) {
            m0 = __hmax2(m0, g_t2h[(size_t)sh[j + 0] * (HID / 2) + tid]);
            m1 = __hmax2(m1, g_t2h[(size_t)sh[j + 1] * (HID / 2) + tid]);
            m2 = __hmax2(m2, g_t2h[(size_t)sh[j + 2] * (HID / 2) + tid]);
            m3 = __hmax2(m3, g_t2h[(size_t)sh[j + 3] * (HID / 2) + tid]);
        }
        for (; j < c; j++)
            m0 = __hmax2(m0, g_t2h[(size_t)sh[j] * (HID / 2) + tid]);
        __syncthreads();
    }
    __half2 m = __hmax2(__hmax2(m0, m1), __hmax2(m2, m3));
    float2 f = __half22float2(m);
    float v0 = (cnt > 0) ? f.x : 0.0f;
    float v1 = (cnt > 0) ? f.y : 0.0f;
    size_t o = (size_t)n * HID + tid * 2;
    g_h[o]     += silu(v0);
    g_h[o + 1] += silu(v1);
}

// ------- global mean pool (batch sorted) + re-zero g_cur for next call -----
__global__ void pool_kernel(const int* __restrict__ batch,
                            float* __restrict__ out) {
    int g = blockIdx.x;          // 0..63
    int tid = threadIdx.x;       // 0..255 feature

    int lo = 0, hi = N_NODES;
    while (lo < hi) { int m = (lo + hi) >> 1; if (batch[m] < g) lo = m + 1; else hi = m; }
    int start = lo;
    lo = start; hi = N_NODES;
    while (lo < hi) { int m = (lo + hi) >> 1; if (batch[m] < g + 1) lo = m + 1; else hi = m; }
    int end = lo;

    float s = 0.0f;
    for (int n = start; n < end; n++)
        s += g_h[(size_t)n * HID + tid];
    float c = (float)(end - start);
    out[g * HID + tid] = s / fmaxf(c, 1.0f);

    // restore invariant: g_cur == 0 for the next kernel_launch invocation
    int z = g * 256 + tid;       // 64*256 = 16384 >= N_NODES
    if (z < N_NODES) g_cur[z] = 0;
}

// ---------------- launch ----------------
extern "C" void kernel_launch(void* const* d_in, const int* in_sizes, int n_in,
                              void* d_out, int out_size) {
    const float* x     = (const float*)d_in[0];
    const int*   ei    = (const int*)d_in[1];
    const int*   batch = (const int*)d_in[2];
    const float* W_emb = (const float*)d_in[3];
    const float* b_emb = (const float*)d_in[4];
    const float* W1a   = (const float*)d_in[5];
    const float* b1a   = (const float*)d_in[6];
    const float* W1b   = (const float*)d_in[7];
    const float* b1b   = (const float*)d_in[8];
    const float* W2a   = (const float*)d_in[9];
    const float* b2a   = (const float*)d_in[10];
    const float* W2b   = (const float*)d_in[11];
    const float* b2b   = (const float*)d_in[12];
    float* out = (float*)d_out;

    const int* src = ei;
    const int* dst = ei + N_EDGES;

    float* h = nullptr; float* t1 = nullptr; __half2* t2h = nullptr;
    cudaGetSymbolAddress((void**)&h,   g_h);
    cudaGetSymbolAddress((void**)&t1,  g_t1);
    cudaGetSymbolAddress((void**)&t2h, g_t2h);

    cudaFuncSetAttribute((const void*)gemm_tc<true,  false>,
        cudaFuncAttributeMaxDynamicSharedMemorySize, GEMM_SMEM_BYTES);
    cudaFuncSetAttribute((const void*)gemm_tc<false, true>,
        cudaFuncAttributeMaxDynamicSharedMemorySize, GEMM_SMEM_BYTES);

    // setup: ELL fill + embed in one grid (overlapped)
    int embed_blocks = (N_NODES * HID + 255) / 256;
    setup_kernel<<<FILL_BLOCKS + embed_blocks, 256>>>(x, W_emb, b_emb, src, dst);

    dim3 ggrid((N_NODES + BM - 1) / BM, HID / BN);

    // conv 1: t1 = relu(h@W1a+b1a); t2h = half(t1@W1b+b1b); h += silu(gather-max)
    gemm_tc<true,  false><<<ggrid, 256, GEMM_SMEM_BYTES>>>(h,  W1a, b1a, t1, nullptr, N_NODES);
    gemm_tc<false, true ><<<ggrid, 256, GEMM_SMEM_BYTES>>>(t1, W1b, b1b, nullptr, t2h, N_NODES);
    agg_kernel<<<N_NODES, 128>>>();

    // conv 2
    gemm_tc<true,  false><<<ggrid, 256, GEMM_SMEM_BYTES>>>(h,  W2a, b2a, t1, nullptr, N_NODES);
    gemm_tc<false, true ><<<ggrid, 256, GEMM_SMEM_BYTES>>>(t1, W2b, b2b, nullptr, t2h, N_NODES);
    agg_kernel<<<N_NODES, 128>>>();

    // global mean pool (+ g_cur re-zero for next call)
    pool_kernel<<<N_GRAPHS, 256>>>(batch, out);
}

// round 7
// speedup vs baseline: 3.1590x; 1.1593x over previous
#include <cuda_runtime.h>
#include <cuda_fp16.h>
#include <cstdint>
#include <math.h>

#define N_NODES 10000
#define N_EDGES 320000
#define N_GRAPHS 64
#define HID 256
#define ELL_CAP 128
#define FILL_BLOCKS 1250           // 1250*256 = 320000 edges

// ---------------- scratch (static __device__, no allocation) ----------------
__device__ __align__(16) float   g_h  [N_NODES * HID];
__device__ __align__(16) __half2 g_t1h[N_NODES * HID / 2];
__device__ __align__(16) __half2 g_t2h[N_NODES * HID / 2];
__device__ int g_cur[N_NODES];          // zero at module load; re-zeroed by pool tail
__device__ __align__(16) int g_ell[N_NODES * ELL_CAP];

__device__ __forceinline__ float silu(float v) {
    return v / (1.0f + expf(-v));
}

__device__ __forceinline__ int clampi(int v, int hi) {
    return v < 0 ? 0 : (v >= hi ? hi - 1 : v);
}

__device__ __forceinline__ unsigned f2tf32(float f) {
    unsigned r;
    asm("cvt.rna.tf32.f32 %0, %1;" : "=r"(r) : "f"(f));
    return r;
}

__device__ __forceinline__ void mma_tf32(float* d, const unsigned* a, const unsigned* b) {
    asm volatile(
        "mma.sync.aligned.m16n8k8.row.col.f32.tf32.tf32.f32 "
        "{%0,%1,%2,%3}, {%4,%5,%6,%7}, {%8,%9}, {%0,%1,%2,%3};"
        : "+f"(d[0]), "+f"(d[1]), "+f"(d[2]), "+f"(d[3])
        : "r"(a[0]), "r"(a[1]), "r"(a[2]), "r"(a[3]),
          "r"(b[0]), "r"(b[1]));
}

__device__ __forceinline__ void mma_f16(float* d, const unsigned* a, const unsigned* b) {
    asm volatile(
        "mma.sync.aligned.m16n8k16.row.col.f32.f16.f16.f32 "
        "{%0,%1,%2,%3}, {%4,%5,%6,%7}, {%8,%9}, {%0,%1,%2,%3};"
        : "+f"(d[0]), "+f"(d[1]), "+f"(d[2]), "+f"(d[3])
        : "r"(a[0]), "r"(a[1]), "r"(a[2]), "r"(a[3]),
          "r"(b[0]), "r"(b[1]));
}

__device__ __forceinline__ void cp16(void* smem_dst, const void* gsrc, bool pred) {
    unsigned s = (unsigned)__cvta_generic_to_shared(smem_dst);
    int szn = pred ? 16 : 0;
    asm volatile("cp.async.ca.shared.global [%0], [%1], 16, %2;"
                 :: "r"(s), "l"(gsrc), "r"(szn));
}

// ------- fused setup: ELL fill (blocks [0,FILL_BLOCKS)) + embed (rest) ------
__global__ void setup_kernel(const float* __restrict__ x,
                             const float* __restrict__ w,
                             const float* __restrict__ b,
                             const int* __restrict__ src,
                             const int* __restrict__ dst) {
    int blk = blockIdx.x;
    if (blk < FILL_BLOCKS) {
        int e = blk * 256 + threadIdx.x;
        if (e < N_EDGES) {
            int d = clampi(dst[e], N_NODES);
            int slot = atomicAdd(&g_cur[d], 1);
            if (slot < ELL_CAP)
                g_ell[d * ELL_CAP + slot] = clampi(src[e], N_NODES);
        }
    } else {
        int idx = (blk - FILL_BLOCKS) * 256 + threadIdx.x;
        if (idx < N_NODES * HID) {
            int n = idx >> 8;
            int d = idx & 255;
            g_h[idx] = silu(x[n] * w[d] + b[d]);
        }
    }
}

// ------------- GEMM-a (tf32): t1h = relu(h[M,256] @ W + bias) as half2 -----
#define BM 64
#define BN 128
#define BK 32
#define AS_STRIDE 36
#define BS_STRIDE 136
#define AS_BUF (BM * AS_STRIDE)   // 2304 floats
#define BS_BUF (BK * BS_STRIDE)   // 4352 floats
#define GEMM_SMEM_BYTES ((2 * AS_BUF + 2 * BS_BUF) * 4)   // 53248

__global__ __launch_bounds__(256, 3)
void gemm_tf32(const float* __restrict__ A,
               const float* __restrict__ W,
               const float* __restrict__ bias,
               __half2* __restrict__ Ch, int M) {
    extern __shared__ float dynsmem[];
    float* As = dynsmem;                 // [2][BM][AS_STRIDE]
    float* Bs = dynsmem + 2 * AS_BUF;    // [2][BK][BS_STRIDE]

    int tid  = threadIdx.x;
    int lane = tid & 31;
    int warp = tid >> 5;
    int wr = (warp & 1) * 32;
    int wc = (warp >> 1) * 32;
    int rowBase = blockIdx.x * BM;
    int colBase = blockIdx.y * BN;
    int g  = lane >> 2;
    int t4 = lane & 3;

    int ar[2], ac[2], br[4], bc[4];
#pragma unroll
    for (int i = 0; i < 2; i++) {
        int l = tid + 256 * i;
        ar[i] = l >> 3;  ac[i] = (l & 7) * 4;
    }
#pragma unroll
    for (int i = 0; i < 4; i++) {
        int l = tid + 256 * i;
        br[i] = l >> 5;  bc[i] = (l & 31) * 4;
    }

    float acc[2][4][4];
#pragma unroll
    for (int mi = 0; mi < 2; mi++)
#pragma unroll
        for (int ni = 0; ni < 4; ni++)
#pragma unroll
            for (int r = 0; r < 4; r++) acc[mi][ni][r] = 0.0f;

#pragma unroll
    for (int i = 0; i < 2; i++) {
        int grow = rowBase + ar[i];
        cp16(&As[ar[i] * AS_STRIDE + ac[i]],
             A + (size_t)grow * HID + ac[i], grow < M);
    }
#pragma unroll
    for (int i = 0; i < 4; i++)
        cp16(&Bs[br[i] * BS_STRIDE + bc[i]],
             W + (size_t)br[i] * HID + colBase + bc[i], true);
    asm volatile("cp.async.commit_group;");

    int buf = 0;
#pragma unroll
    for (int kt = 0; kt < HID / BK; kt++) {
        asm volatile("cp.async.wait_group 0;");
        __syncthreads();

        if (kt < HID / BK - 1) {
            int k2 = (kt + 1) * BK;
            float* Ad = As + (buf ^ 1) * AS_BUF;
            float* Bd = Bs + (buf ^ 1) * BS_BUF;
#pragma unroll
            for (int i = 0; i < 2; i++) {
                int grow = rowBase + ar[i];
                cp16(&Ad[ar[i] * AS_STRIDE + ac[i]],
                     A + (size_t)grow * HID + k2 + ac[i], grow < M);
            }
#pragma unroll
            for (int i = 0; i < 4; i++)
                cp16(&Bd[br[i] * BS_STRIDE + bc[i]],
                     W + (size_t)(k2 + br[i]) * HID + colBase + bc[i], true);
            asm volatile("cp.async.commit_group;");
        }

        const float* Ab = As + buf * AS_BUF;
        const float* Bb = Bs + buf * BS_BUF;
#pragma unroll
        for (int s = 0; s < 4; s++) {
            int k0 = s * 8;
            unsigned a[2][4], b[4][2];
#pragma unroll
            for (int mi = 0; mi < 2; mi++) {
                int m0 = wr + mi * 16;
                a[mi][0] = f2tf32(Ab[(m0 + g    ) * AS_STRIDE + k0 + t4    ]);
                a[mi][1] = f2tf32(Ab[(m0 + g + 8) * AS_STRIDE + k0 + t4    ]);
                a[mi][2] = f2tf32(Ab[(m0 + g    ) * AS_STRIDE + k0 + t4 + 4]);
                a[mi][3] = f2tf32(Ab[(m0 + g + 8) * AS_STRIDE + k0 + t4 + 4]);
            }
#pragma unroll
            for (int ni = 0; ni < 4; ni++) {
                int n0 = wc + ni * 8;
                b[ni][0] = f2tf32(Bb[(k0 + t4    ) * BS_STRIDE + n0 + g]);
                b[ni][1] = f2tf32(Bb[(k0 + t4 + 4) * BS_STRIDE + n0 + g]);
            }
#pragma unroll
            for (int mi = 0; mi < 2; mi++)
#pragma unroll
                for (int ni = 0; ni < 4; ni++)
                    mma_tf32(acc[mi][ni], a[mi], b[ni]);
        }
        buf ^= 1;
    }

    // epilogue: bias + relu -> half2
#pragma unroll
    for (int mi = 0; mi < 2; mi++) {
        int row0 = rowBase + wr + mi * 16 + g;
        int row1 = row0 + 8;
#pragma unroll
        for (int ni = 0; ni < 4; ni++) {
            int col = colBase + wc + ni * 8 + t4 * 2;
            float b0 = bias[col], b1 = bias[col + 1];
            float v00 = fmaxf(acc[mi][ni][0] + b0, 0.f);
            float v01 = fmaxf(acc[mi][ni][1] + b1, 0.f);
            float v10 = fmaxf(acc[mi][ni][2] + b0, 0.f);
            float v11 = fmaxf(acc[mi][ni][3] + b1, 0.f);
            if (row0 < M)
                Ch[(size_t)row0 * (HID / 2) + (col >> 1)] = __floats2half2_rn(v00, v01);
            if (row1 < M)
                Ch[(size_t)row1 * (HID / 2) + (col >> 1)] = __floats2half2_rn(v10, v11);
        }
    }
}

// ------------- GEMM-b (fp16): t2h = t1h[M,256] @ W + bias -----------------
// A in half2 (cp.async); B converted f32->half2 k-pairs during load, reg-prefetched.
#define AS2_STRIDE 20    // half2 units (80 B/row)
#define BS2_STRIDE 136   // half2 units
#define AS2_BUF (BM * AS2_STRIDE)        // 1280 half2
#define BS2_BUF (16 * BS2_STRIDE)        // 2176 half2
#define GEMMH_SMEM_BYTES ((2 * AS2_BUF + 2 * BS2_BUF) * 4)   // 27648

__global__ __launch_bounds__(256, 3)
void gemm_fp16(const __half2* __restrict__ A,
               const float* __restrict__ W,
               const float* __restrict__ bias,
               __half2* __restrict__ Ch, int M) {
    extern __shared__ __half2 dynsmem2[];
    __half2* As2 = dynsmem2;                  // [2][BM][AS2_STRIDE]
    __half2* Bs2 = dynsmem2 + 2 * AS2_BUF;    // [2][16][BS2_STRIDE]

    int tid  = threadIdx.x;
    int lane = tid & 31;
    int warp = tid >> 5;
    int wr = (warp & 1) * 32;
    int wc = (warp >> 1) * 32;
    int rowBase = blockIdx.x * BM;
    int colBase = blockIdx.y * BN;
    int g  = lane >> 2;
    int t4 = lane & 3;

    // A: 64 rows x 16 half2 = 1024 half2 -> 1x 16B per thread
    int arow = tid >> 2;             // 0..63
    int acq  = (tid & 3) * 4;        // half2 idx 0,4,8,12
    // B: tasks: kp = 0..15, nq (n offset, mult of 4)
    int kp0 = tid >> 5;              // task i=0: kp 0..7
    int nq0 = (tid & 31) * 4;
    int kp1 = kp0 + 8;               // task i=1
    int nq1 = nq0;

    float acc[2][4][4];
#pragma unroll
    for (int mi = 0; mi < 2; mi++)
#pragma unroll
        for (int ni = 0; ni < 4; ni++)
#pragma unroll
            for (int r = 0; r < 4; r++) acc[mi][ni][r] = 0.0f;

    // ---- prologue: A tile0 cp.async, B tile0 -> regs ----
    {
        int grow = rowBase + arow;
        cp16(&As2[arow * AS2_STRIDE + acq],
             A + (size_t)grow * (HID / 2) + acq, grow < M);
        asm volatile("cp.async.commit_group;");
    }
    __half2 breg[2][4];
    {
#pragma unroll
        for (int i = 0; i < 2; i++) {
            int kp = (i == 0) ? kp0 : kp1, nq = nq0;
            float4 v0 = *(const float4*)(W + (size_t)(2 * kp    ) * HID + colBase + nq);
            float4 v1 = *(const float4*)(W + (size_t)(2 * kp + 1) * HID + colBase + nq);
            breg[i][0] = __floats2half2_rn(v0.x, v1.x);
            breg[i][1] = __floats2half2_rn(v0.y, v1.y);
            breg[i][2] = __floats2half2_rn(v0.z, v1.z);
            breg[i][3] = __floats2half2_rn(v0.w, v1.w);
        }
    }

    int buf = 0;
#pragma unroll
    for (int kt = 0; kt < HID / BK; kt++) {
        asm volatile("cp.async.wait_group 0;");
        __syncthreads();                    // A(kt) visible; compute(kt-1) done

        // store B regs for this tile
        __half2* Bd = Bs2 + buf * BS2_BUF;
        *(float4*)&Bd[kp0 * BS2_STRIDE + nq0] = *(float4*)&breg[0][0];
        *(float4*)&Bd[kp1 * BS2_STRIDE + nq1] = *(float4*)&breg[1][0];

        if (kt < HID / BK - 1) {
            int k2 = (kt + 1) * BK;
            // A next tile
            int grow = rowBase + arow;
            cp16(&As2[(buf ^ 1) * AS2_BUF + arow * AS2_STRIDE + acq],
                 A + (size_t)grow * (HID / 2) + k2 / 2 + acq, grow < M);
            asm volatile("cp.async.commit_group;");
            // B next tile -> regs (overlaps compute below)
#pragma unroll
            for (int i = 0; i < 2; i++) {
                int kp = (i == 0) ? kp0 : kp1, nq = nq0;
                float4 v0 = *(const float4*)(W + (size_t)(k2 + 2 * kp    ) * HID + colBase + nq);
                float4 v1 = *(const float4*)(W + (size_t)(k2 + 2 * kp + 1) * HID + colBase + nq);
                breg[i][0] = __floats2half2_rn(v0.x, v1.x);
                breg[i][1] = __floats2half2_rn(v0.y, v1.y);
                breg[i][2] = __floats2half2_rn(v0.z, v1.z);
                breg[i][3] = __floats2half2_rn(v0.w, v1.w);
            }
        }
        __syncthreads();                    // B(kt) STS visible

        const __half2* Ab = As2 + buf * AS2_BUF;
        const __half2* Bb = Bs2 + buf * BS2_BUF;
#pragma unroll
        for (int s = 0; s < 2; s++) {       // two k16 steps per 32-k tile
            int ko = s * 8;                 // half2 offset
            unsigned a[2][4], b[4][2];
#pragma unroll
            for (int mi = 0; mi < 2; mi++) {
                int m0 = wr + mi * 16;
                a[mi][0] = *(const unsigned*)&Ab[(m0 + g    ) * AS2_STRIDE + ko + t4    ];
                a[mi][1] = *(const unsigned*)&Ab[(m0 + g + 8) * AS2_STRIDE + ko + t4    ];
                a[mi][2] = *(const unsigned*)&Ab[(m0 + g    ) * AS2_STRIDE + ko + t4 + 4];
                a[mi][3] = *(const unsigned*)&Ab[(m0 + g + 8) * AS2_STRIDE + ko + t4 + 4];
            }
#pragma unroll
            for (int ni = 0; ni < 4; ni++) {
                int n0 = wc + ni * 8;
                b[ni][0] = *(const unsigned*)&Bb[(ko + t4    ) * BS2_STRIDE + n0 + g];
                b[ni][1] = *(const unsigned*)&Bb[(ko + t4 + 4) * BS2_STRIDE + n0 + g];
            }
#pragma unroll
            for (int mi = 0; mi < 2; mi++)
#pragma unroll
                for (int ni = 0; ni < 4; ni++)
                    mma_f16(acc[mi][ni], a[mi], b[ni]);
        }
        buf ^= 1;
    }

    // epilogue: bias (no relu) -> half2
#pragma unroll
    for (int mi = 0; mi < 2; mi++) {
        int row0 = rowBase + wr + mi * 16 + g;
        int row1 = row0 + 8;
#pragma unroll
        for (int ni = 0; ni < 4; ni++) {
            int col = colBase + wc + ni * 8 + t4 * 2;
            float b0 = bias[col], b1 = bias[col + 1];
            if (row0 < M)
                Ch[(size_t)row0 * (HID / 2) + (col >> 1)] =
                    __floats2half2_rn(acc[mi][ni][0] + b0, acc[mi][ni][1] + b1);
            if (row1 < M)
                Ch[(size_t)row1 * (HID / 2) + (col >> 1)] =
                    __floats2half2_rn(acc[mi][ni][2] + b0, acc[mi][ni][3] + b1);
        }
    }
}

// ------- edge aggregation: warp-per-node float4 gather-max ------------------
// block = 256 (8 warps = 8 nodes), grid = 1250. Lane owns 16B of 512B row.
__global__ void agg_kernel() {
    const unsigned FULL = 0xffffffffu;
    int warp = threadIdx.x >> 5;
    int lane = threadIdx.x & 31;
    int n = blockIdx.x * 8 + warp;
    if (n >= N_NODES) return;

    int cnt = min(g_cur[n], ELL_CAP);
    const int* lst = g_ell + n * ELL_CAP;
    const float4* t2v = (const float4*)g_t2h;   // 32 float4 per row

    unsigned ninf = 0xFC00FC00u;
    __half2 mneg = *(__half2*)&ninf;
    __half2 m[8];
#pragma unroll
    for (int q = 0; q < 8; q++) m[q] = mneg;

    for (int base = 0; base < cnt; base += 32) {
        int e = base + lane;
        int idx = (e < cnt) ? lst[e] : 0;
        int c = min(32, cnt - base);
        int j = 0;
        for (; j + 2 <= c; j += 2) {
            int s0 = __shfl_sync(FULL, idx, j);
            int s1 = __shfl_sync(FULL, idx, j + 1);
            float4 v0 = t2v[s0 * 32 + lane];
            float4 v1 = t2v[s1 * 32 + lane];
            m[0] = __hmax2(m[0], *(__half2*)&v0.x);
            m[1] = __hmax2(m[1], *(__half2*)&v0.y);
            m[2] = __hmax2(m[2], *(__half2*)&v0.z);
            m[3] = __hmax2(m[3], *(__half2*)&v0.w);
            m[4] = __hmax2(m[4], *(__half2*)&v1.x);
            m[5] = __hmax2(m[5], *(__half2*)&v1.y);
            m[6] = __hmax2(m[6], *(__half2*)&v1.z);
            m[7] = __hmax2(m[7], *(__half2*)&v1.w);
        }
        if (j < c) {
            int s0 = __shfl_sync(FULL, idx, j);
            float4 v0 = t2v[s0 * 32 + lane];
            m[0] = __hmax2(m[0], *(__half2*)&v0.x);
            m[1] = __hmax2(m[1], *(__half2*)&v0.y);
            m[2] = __hmax2(m[2], *(__half2*)&v0.z);
            m[3] = __hmax2(m[3], *(__half2*)&v0.w);
        }
    }
#pragma unroll
    for (int q = 0; q < 4; q++) m[q] = __hmax2(m[q], m[q + 4]);

    // lane owns features [lane*8, lane*8+8)
    float f[8];
#pragma unroll
    for (int q = 0; q < 4; q++) {
        float2 p = __half22float2(m[q]);
        f[2 * q]     = (cnt > 0) ? p.x : 0.0f;
        f[2 * q + 1] = (cnt > 0) ? p.y : 0.0f;
    }
    float4* hp = (float4*)(g_h + (size_t)n * HID) + lane * 2;
    float4 h0 = hp[0], h1 = hp[1];
    h0.x += silu(f[0]); h0.y += silu(f[1]); h0.z += silu(f[2]); h0.w += silu(f[3]);
    h1.x += silu(f[4]); h1.y += silu(f[5]); h1.z += silu(f[6]); h1.w += silu(f[7]);
    hp[0] = h0; hp[1] = h1;
}

// ------- global mean pool (batch sorted) + re-zero g_cur for next call -----
__global__ void pool_kernel(const int* __restrict__ batch,
                            float* __restrict__ out) {
    int g = blockIdx.x;          // 0..63
    int tid = threadIdx.x;       // 0..255 feature

    int lo = 0, hi = N_NODES;
    while (lo < hi) { int m = (lo + hi) >> 1; if (batch[m] < g) lo = m + 1; else hi = m; }
    int start = lo;
    lo = start; hi = N_NODES;
    while (lo < hi) { int m = (lo + hi) >> 1; if (batch[m] < g + 1) lo = m + 1; else hi = m; }
    int end = lo;

    float s = 0.0f;
    for (int n = start; n < end; n++)
        s += g_h[(size_t)n * HID + tid];
    float c = (float)(end - start);
    out[g * HID + tid] = s / fmaxf(c, 1.0f);

    int z = g * 256 + tid;       // 64*256 = 16384 >= N_NODES
    if (z < N_NODES) g_cur[z] = 0;
}

// ---------------- launch ----------------
extern "C" void kernel_launch(void* const* d_in, const int* in_sizes, int n_in,
                              void* d_out, int out_size) {
    const float* x     = (const float*)d_in[0];
    const int*   ei    = (const int*)d_in[1];
    const int*   batch = (const int*)d_in[2];
    const float* W_emb = (const float*)d_in[3];
    const float* b_emb = (const float*)d_in[4];
    const float* W1a   = (const float*)d_in[5];
    const float* b1a   = (const float*)d_in[6];
    const float* W1b   = (const float*)d_in[7];
    const float* b1b   = (const float*)d_in[8];
    const float* W2a   = (const float*)d_in[9];
    const float* b2a   = (const float*)d_in[10];
    const float* W2b   = (const float*)d_in[11];
    const float* b2b   = (const float*)d_in[12];
    float* out = (float*)d_out;

    const int* src = ei;
    const int* dst = ei + N_EDGES;

    float* h = nullptr; __half2* t1h = nullptr; __half2* t2h = nullptr;
    cudaGetSymbolAddress((void**)&h,   g_h);
    cudaGetSymbolAddress((void**)&t1h, g_t1h);
    cudaGetSymbolAddress((void**)&t2h, g_t2h);

    cudaFuncSetAttribute((const void*)gemm_tf32,
        cudaFuncAttributeMaxDynamicSharedMemorySize, GEMM_SMEM_BYTES);

    // setup: ELL fill + embed in one grid (overlapped)
    int embed_blocks = (N_NODES * HID + 255) / 256;
    setup_kernel<<<FILL_BLOCKS + embed_blocks, 256>>>(x, W_emb, b_emb, src, dst);

    dim3 ggrid((N_NODES + BM - 1) / BM, HID / BN);

    // conv 1
    gemm_tf32<<<ggrid, 256, GEMM_SMEM_BYTES>>>(h, W1a, b1a, t1h, N_NODES);
    gemm_fp16<<<ggrid, 256, GEMMH_SMEM_BYTES>>>(t1h, W1b, b1b, t2h, N_NODES);
    agg_kernel<<<1250, 256>>>();

    // conv 2
    gemm_tf32<<<ggrid, 256, GEMM_SMEM_BYTES>>>(h, W2a, b2a, t1h, N_NODES);
    gemm_fp16<<<ggrid, 256, GEMMH_SMEM_BYTES>>>(t1h, W2b, b2b, t2h, N_NODES);
    agg_kernel<<<1250, 256>>>();

    // global mean pool (+ g_cur re-zero for next call)
    pool_kernel<<<N_GRAPHS, 256>>>(batch, out);
}